// round 16
// baseline (speedup 1.0000x reference)
#include <cuda_runtime.h>
#include <cstdint>

// ButterflyRotationLayer: R = B(d,d) @ B(d,d/2) @ ... @ B(d,2), d=4096, 12 stages.
//
// Split at k=64:
//   H = stages k=4096..128 : H[r,l] != 0 only when l == r (mod 64).
//       For fixed r6 = r&63, the 64 rows {r6+64*rh} share ONE 64x64 m-space
//       butterfly matrix Hhat_{r6}[rh, m].
//   T = stages k=64..2     : block-diagonal, 64 independent 64x64 matrices That_B.
// Exactly one l contributes per output element:
//   R[r6+64*rh, 64*B+cc] = Hhat_{r6}[rh, B] * That_B[r6, cc]
//
// Measured ceilings (rounds 7-15): outer stage ~13.2us across all store paths
// (v4 STG / SMEM-staged / TMA bulk / __stcs / v8 evict_last) -> L2 write-port
// cap. Remaining outer inefficiency: 2048 blocks = 1.73 waves at 8/SM.
// This version: SINGLE-WAVE outer (1024 blocks, 16 rows/thread in two 8-row
// passes, t-float4 loaded once and reused) -> no wave transition, no ragged
// tail. Mats: 512-block 4-way split (best measured). Plain launches.

#define D 4096

// g_H[r*64 + m]  = Hhat_{r&63}[r>>6, m]
__device__ __align__(16) float g_H[D * 64];
// g_T[(B*64+rr)*64 + cc] = That_B[rr, cc]
__device__ __align__(16) float g_T[D * 64];

// ---------------------------------------------------------------------------
// Kernel 1: 512 blocks. Block b -> matrix mat=b>>2 (head if mat<64 else tail),
// row quarter qf=b&3 (rows qf*16 .. qf*16+15). M = I restricted to 16 rows;
// stages apply column Givens rotations. All 192 (c,s) pairs computed in
// parallel upfront (theta indices depend only on mat).
// ---------------------------------------------------------------------------
__global__ __launch_bounds__(256) void butterfly_mats_kernel(const float* __restrict__ thetas) {
    __shared__ float sm[16][65];
    __shared__ float cs_c[6][32], cs_s[6][32];

    const int tid = threadIdx.x;
    const int b   = blockIdx.x;
    const int mat = b >> 2;
    const int qf  = b & 3;
    const bool is_head = (mat < 64);

    if (tid < 192) {
        const int ii   = tid >> 5;
        const int j    = tid & 31;
        const int half = 32 >> ii;
        const int bm   = j >> (5 - ii);
        const int jm   = j & (half - 1);
        const int p_loc = (bm << (6 - ii)) + jm;
        int theta_idx;
        if (is_head) {
            const int p    = mat + (p_loc << 6);
            const int logk = 12 - ii;
            const int hh   = 2048 >> ii;
            theta_idx = ii * 2048 + (p >> logk) * hh + (p & ((1 << logk) - 1));
        } else {
            const int p    = ((mat - 64) << 6) + p_loc;
            const int logk = 6 - ii;
            const int hh   = 32 >> ii;
            theta_idx = (ii + 6) * 2048 + (p >> logk) * hh + (p & ((1 << logk) - 1));
        }
        float s, c;
        sincosf(thetas[theta_idx], &s, &c);
        cs_c[ii][j] = c;
        cs_s[ii][j] = s;
    }

    // identity restricted to rows [qf*16, qf*16+16)
#pragma unroll
    for (int k = 0; k < 4; ++k) {
        const int e  = tid + k * 256;            // 0..1023
        const int lr = e >> 6;                   // local row 0..15
        const int m  = e & 63;
        sm[lr][m] = (((qf << 4) + lr) == m) ? 1.0f : 0.0f;
    }
    __syncthreads();

    const int j = tid & 31;

#pragma unroll
    for (int ii = 0; ii < 6; ++ii) {
        const int half  = 32 >> ii;
        const int bm    = j >> (5 - ii);
        const int jm    = j & (half - 1);
        const int p_loc = (bm << (6 - ii)) + jm;
        const int q_loc = p_loc + half;
        const float c = cs_c[ii][j];
        const float s = cs_s[ii][j];
#pragma unroll
        for (int k = 0; k < 2; ++k) {
            const int lr = (tid >> 5) + (k << 3);   // local row 0..15
            const float a  = sm[lr][p_loc];
            const float bb = sm[lr][q_loc];
            sm[lr][p_loc] = c * a + s * bb;
            sm[lr][q_loc] = c * bb - s * a;
        }
        __syncthreads();
    }

    if (is_head) {
        // g_H[(r6 + 64*rh)*64 + m] = Hhat_{r6=mat}[rh, m], rh = qf*16 + lr
#pragma unroll
        for (int k = 0; k < 4; ++k) {
            const int e  = tid + k * 256;
            const int lr = e >> 6;
            const int m  = e & 63;
            const int rh = (qf << 4) + lr;
            g_H[(mat << 6) + (rh << 12) + m] = sm[lr][m];
        }
    } else {
        // g_T[((mat-64)*64 + rr)*64 + cc], rr = qf*16 + lr -> contiguous 4KB
        const int base = ((mat - 64) << 12) + (qf << 10);
#pragma unroll
        for (int k = 0; k < 4; ++k) {
            const int e = tid + k * 256;
            g_T[base + e] = sm[e >> 6][e & 63];
        }
    }
}

// ---------------------------------------------------------------------------
// Kernel 2: SINGLE-WAVE outer product. 1024 blocks x 256 threads, 8 blocks/SM.
// Block b -> (r6 = (b>>2)&63, ch = b&3, gpair = b>>8 in 0..3). Thread owns one
// float4 column slot c4; t = That_B[r6, c&63] loaded ONCE. Two 8-row passes:
// rows r = r6 + 64*(8*(2*gpair+half) + jr), jr = 0..7.
//   R[r, c..c+3] = g_H[r*64 + B] * t
// ---------------------------------------------------------------------------
__global__ __launch_bounds__(256, 8) void outer_product_kernel(float4* __restrict__ out) {
    const int b     = blockIdx.x;                     // 0..1023
    const int c4    = ((b & 3) << 8) | threadIdx.x;   // 0..1023 (float4 within row)
    const int r6    = (b >> 2) & 63;
    const int gpair = b >> 8;                         // 0..3
    const int c     = c4 << 2;
    const int B     = c >> 6;

    const int l = (B << 6) + r6;
    const float4 t = *reinterpret_cast<const float4*>(&g_T[(l << 6) + (c & 63)]);

#pragma unroll
    for (int half = 0; half < 2; ++half) {
        const int g  = (gpair << 1) + half;           // 0..7
        const int r0 = r6 + (g << 9);                 // rows r0 + 64*jr

        const float* __restrict__ hp = &g_H[(r0 << 6) + B];
        float h[8];
#pragma unroll
        for (int jr = 0; jr < 8; ++jr)
            h[jr] = hp[jr << 12];                     // +jr*4096 floats (16 KB)

        float4* __restrict__ o = out + (((long)r0 << 10) + c4);
#pragma unroll
        for (int jr = 0; jr < 8; ++jr) {
            const float hh = h[jr];
            o[(long)jr << 16] = make_float4(hh * t.x, hh * t.y, hh * t.z, hh * t.w);
        }
    }
}

extern "C" void kernel_launch(void* const* d_in, const int* in_sizes, int n_in,
                              void* d_out, int out_size) {
    const float* thetas = (const float*)d_in[0];  // [12, 2048] fp32
    float4* out = (float4*)d_out;                 // [4096, 4096] fp32

    butterfly_mats_kernel<<<512, 256>>>(thetas);
    outer_product_kernel<<<1024, 256>>>(out);
}